// round 17
// baseline (speedup 1.0000x reference)
#include <cuda_runtime.h>
#include <math.h>
#include <stdint.h>

#define NBLK    256        // CTAs, 32 rows each
#define THREADS 256
#define F_IN    512
#define H_DIM   256
#define W_DIM   64

// smem float offsets
#define O_ACT  0            // 64 A-frags * 132 = 8448 (X 2-bufs 2*1056 alias front)
#define O_B    8448         // 2 B slabs * 8192
#define O_C    24832        // b1(256) b2(256) bq(64) wh(64) red(8) flg(1)
#define SMEMF  25482
#define SMEM_BYTES (SMEMF * 4)   // 101928 B -> 2 CTAs/SM

static __device__ float g_Wf[212992];   // W1|W2|Wq, tf32-rounded, FRAGMENT-MAJOR
static __device__ float g_part[NBLK];
static __device__ unsigned int g_cnt = 0;

__device__ __forceinline__ float f2tf(float f) {
    uint32_t r;
    asm("cvt.rna.tf32.f32 %0, %1;" : "=r"(r) : "f"(f));
    return __uint_as_float(r);
}
__device__ __forceinline__ void cpa16(uint32_t dst, const float* src) {
    asm volatile("cp.async.cg.shared.global [%0], [%1], 16;" :: "r"(dst), "l"(src));
}
#define CPA_COMMIT() asm volatile("cp.async.commit_group;" ::: "memory")
template<int N> __device__ __forceinline__ void cpa_wait() {
    asm volatile("cp.async.wait_group %0;" :: "n"(N) : "memory");
}
// D(16x8) += A(16x8,row) * B(8x8,col)   tf32
__device__ __forceinline__ void mma8(float* d, const uint4& a, uint32_t b0, uint32_t b1) {
    asm volatile("mma.sync.aligned.m16n8k8.row.col.f32.tf32.tf32.f32 "
                 "{%0,%1,%2,%3}, {%4,%5,%6,%7}, {%8,%9}, {%0,%1,%2,%3};"
                 : "+f"(d[0]), "+f"(d[1]), "+f"(d[2]), "+f"(d[3])
                 : "r"(a.x), "r"(a.y), "r"(a.z), "r"(a.w), "r"(b0), "r"(b1));
}

// conv_w: tf32-round weights AND permute to fragment-major B layout.
// frag idx = kt*NT + nt ; element = (fragIdx*32 + g*4 + tg)*4 + half*2 + bb
__global__ void conv_w(const float* __restrict__ W1, const float* __restrict__ W2,
                       const float* __restrict__ Wq)
{
    const int i = blockIdx.x * blockDim.x + threadIdx.x;
    if (i >= 53248) return;
    const float4* src; int off, base, NT, k, c;
    if (i < 32768)      { src = (const float4*)W1; off = i;          base = 0;      NT = 16; k = off >> 6; c = (off & 63) * 4; }
    else if (i < 49152) { src = (const float4*)W2; off = i - 32768;  base = 131072; NT = 16; k = off >> 6; c = (off & 63) * 4; }
    else                { src = (const float4*)Wq; off = i - 49152;  base = 196608; NT = 4;  k = off >> 4; c = (off & 15) * 4; }
    float4 v = src[off];
    float vv[4] = { v.x, v.y, v.z, v.w };
    const int kt = k >> 3, rr = k & 7, tg = rr & 3, bb = rr >> 2;
    #pragma unroll
    for (int e = 0; e < 4; ++e) {
        const int cc = c + e, nt = cc >> 4, w16 = cc & 15, g = w16 & 7, hf = w16 >> 3;
        g_Wf[base + ((kt * NT + nt) * 32 + g * 4 + tg) * 4 + hf * 2 + bb] = f2tf(vv[e]);
    }
}

__global__ void __launch_bounds__(THREADS, 2)
fused_mma(const float* __restrict__ X,
          const float* __restrict__ b1, const float* __restrict__ b2,
          const float* __restrict__ bq, const float* __restrict__ Wh,
          const float* __restrict__ bh, float* __restrict__ out)
{
    extern __shared__ float sm[];
    float* sAct = sm;
    float* sB   = sm + O_B;
    float* b1s  = sm + O_C;
    float* b2s  = b1s + 256;
    float* bqs  = b2s + 256;
    float* whs  = bqs + 64;
    float* red  = whs + 64;
    float* flg  = red + 8;
    const uint32_t sb32 = (uint32_t)__cvta_generic_to_shared(sm);

    const int t = threadIdx.x;
    const int w = t >> 5, lane = t & 31;
    const int g = lane >> 2, tg = lane & 3;
    const int row0 = blockIdx.x * 32;

    b1s[t] = b1[t];
    b2s[t] = b2[t];
    if (t < 64) { bqs[t] = bq[t]; whs[t] = Wh[t]; }

    const float* W1f = g_Wf;
    const float* W2f = g_Wf + 131072;
    const float* Wqf = g_Wf + 196608;

    // X slab 32x32 -> fragment-major (fragIdx = mt*4+ktL, stride 132), tf32-rounded
    auto fillX = [&](int s, int buf) {
        const int r = t >> 3, c4 = t & 7;          // 256 f4, one per thread
        float4 v = *reinterpret_cast<const float4*>(X + (size_t)(row0 + r) * F_IN + s * 32 + c4 * 4);
        const int mt = r >> 4, gg = r & 7, rowH = (r >> 3) & 1;
        const int ktL = c4 >> 1, i0 = (c4 & 1) * 2 + rowH;
        float* dst = sm + buf * 1056 + (mt * 4 + ktL) * 132 + gg * 16 + i0;
        dst[0]  = f2tf(v.x);
        dst[4]  = f2tf(v.y);
        dst[8]  = f2tf(v.z);
        dst[12] = f2tf(v.w);
    };
    // weight slab: linear cp.async of pre-permuted global (K-32 slab is contiguous)
    auto fillB = [&](const float* __restrict__ src, int nf4, int buf) {
        const uint32_t dst = sb32 + (O_B + buf * 8192) * 4;
        #pragma unroll
        for (int q = 0; q < 8; ++q) {
            const int idx = t + q * 256;
            if (idx < nf4) cpa16(dst + idx * 16, src + idx * 4);
        }
    };

    // warp tile L1/L2: m32 (2 m-frags) x n32 (n-tile pair {2w, 2w+1})
    float acc[2][4][4];
    #pragma unroll
    for (int i = 0; i < 2; ++i)
        #pragma unroll
        for (int j = 0; j < 4; ++j)
            #pragma unroll
            for (int e = 0; e < 4; ++e) acc[i][j][e] = 0.0f;

    // ============ Layer 1: K=512, 16 slabs of 32 ============
    fillX(0, 0); fillB(W1f, 2048, 0); CPA_COMMIT();
    for (int s = 0; s < 16; ++s) {
        const int cb = s & 1;
        cpa_wait<0>();
        __syncthreads();
        if (s < 15) { fillX(s + 1, cb ^ 1); fillB(W1f + (s + 1) * 8192, 2048, cb ^ 1); CPA_COMMIT(); }
        const float* ax = sm + cb * 1056;
        const float* bx = sB + cb * 8192;
        #pragma unroll
        for (int kk = 0; kk < 4; ++kk) {
            uint4 a0 = *reinterpret_cast<const uint4*>(ax + (0 * 4 + kk) * 132 + lane * 4);
            uint4 a1 = *reinterpret_cast<const uint4*>(ax + (1 * 4 + kk) * 132 + lane * 4);
            uint4 bA = *reinterpret_cast<const uint4*>(bx + (kk * 16 + 2 * w + 0) * 128 + lane * 4);
            uint4 bB = *reinterpret_cast<const uint4*>(bx + (kk * 16 + 2 * w + 1) * 128 + lane * 4);
            mma8(acc[0][0], a0, bA.x, bA.y);
            mma8(acc[0][1], a0, bA.z, bA.w);
            mma8(acc[0][2], a0, bB.x, bB.y);
            mma8(acc[0][3], a0, bB.z, bB.w);
            mma8(acc[1][0], a1, bA.x, bA.y);
            mma8(acc[1][1], a1, bA.z, bA.w);
            mma8(acc[1][2], a1, bB.x, bB.y);
            mma8(acc[1][3], a1, bB.z, bB.w);
        }
    }
    // ---- boundary 1: bias+relu+round, store into act A-frag layout ----
    __syncthreads();
    fillB(W2f, 2048, 0); CPA_COMMIT();
    {
        const int offC0 = g * 16 + ((2 * tg) & 3) * 4 + ((tg >= 2) ? 2 : 0);
        const int offC1 = g * 16 + ((2 * tg + 1) & 3) * 4 + ((tg >= 2) ? 2 : 0);
        #pragma unroll
        for (int i = 0; i < 2; ++i) {
            #pragma unroll
            for (int j = 0; j < 4; ++j) {
                const int kt = w * 4 + j;                  // n8-tile j at cols w*32 + j*8
                const int col0 = w * 32 + j * 8 + 2 * tg;
                float* base = sAct + (i * 32 + kt) * 132;
                const float bA = b1s[col0], bB = b1s[col0 + 1];
                float v0 = f2tf(fmaxf(acc[i][j][0] + bA, 0.0f));
                float v2 = f2tf(fmaxf(acc[i][j][2] + bA, 0.0f));
                float v1 = f2tf(fmaxf(acc[i][j][1] + bB, 0.0f));
                float v3 = f2tf(fmaxf(acc[i][j][3] + bB, 0.0f));
                *reinterpret_cast<float2*>(base + offC0) = make_float2(v0, v2);
                *reinterpret_cast<float2*>(base + offC1) = make_float2(v1, v3);
            }
        }
    }

    // ============ Layer 2: K=256, 8 slabs ============
    #pragma unroll
    for (int i = 0; i < 2; ++i)
        #pragma unroll
        for (int j = 0; j < 4; ++j)
            #pragma unroll
            for (int e = 0; e < 4; ++e) acc[i][j][e] = 0.0f;
    for (int s = 0; s < 8; ++s) {
        const int cb = s & 1;
        cpa_wait<0>();
        __syncthreads();                          // publishes boundary-1 stores at s==0
        if (s < 7) { fillB(W2f + (s + 1) * 8192, 2048, cb ^ 1); CPA_COMMIT(); }
        const float* bx = sB + cb * 8192;
        #pragma unroll
        for (int kk = 0; kk < 4; ++kk) {
            uint4 a0 = *reinterpret_cast<const uint4*>(sAct + (0 * 32 + s * 4 + kk) * 132 + lane * 4);
            uint4 a1 = *reinterpret_cast<const uint4*>(sAct + (1 * 32 + s * 4 + kk) * 132 + lane * 4);
            uint4 bA = *reinterpret_cast<const uint4*>(bx + (kk * 16 + 2 * w + 0) * 128 + lane * 4);
            uint4 bB = *reinterpret_cast<const uint4*>(bx + (kk * 16 + 2 * w + 1) * 128 + lane * 4);
            mma8(acc[0][0], a0, bA.x, bA.y);
            mma8(acc[0][1], a0, bA.z, bA.w);
            mma8(acc[0][2], a0, bB.x, bB.y);
            mma8(acc[0][3], a0, bB.z, bB.w);
            mma8(acc[1][0], a1, bA.x, bA.y);
            mma8(acc[1][1], a1, bA.z, bA.w);
            mma8(acc[1][2], a1, bB.x, bB.y);
            mma8(acc[1][3], a1, bB.z, bB.w);
        }
    }
    // ---- boundary 2: bias+relu+round, store act2 in place ----
    __syncthreads();
    fillB(Wqf, 512, 0); CPA_COMMIT();
    {
        const int offC0 = g * 16 + ((2 * tg) & 3) * 4 + ((tg >= 2) ? 2 : 0);
        const int offC1 = g * 16 + ((2 * tg + 1) & 3) * 4 + ((tg >= 2) ? 2 : 0);
        #pragma unroll
        for (int i = 0; i < 2; ++i) {
            #pragma unroll
            for (int j = 0; j < 4; ++j) {
                const int kt = w * 4 + j;
                const int col0 = w * 32 + j * 8 + 2 * tg;
                float* base = sAct + (i * 32 + kt) * 132;
                const float bA = b2s[col0], bB = b2s[col0 + 1];
                float v0 = f2tf(fmaxf(acc[i][j][0] + bA, 0.0f));
                float v2 = f2tf(fmaxf(acc[i][j][2] + bA, 0.0f));
                float v1 = f2tf(fmaxf(acc[i][j][1] + bB, 0.0f));
                float v3 = f2tf(fmaxf(acc[i][j][3] + bB, 0.0f));
                *reinterpret_cast<float2*>(base + offC0) = make_float2(v0, v2);
                *reinterpret_cast<float2*>(base + offC1) = make_float2(v1, v3);
            }
        }
    }

    // ============ Layer 3: K=256, 8 slabs, N=64; warp tile m16 x n16 ============
    const int mi3 = w >> 2, nj3 = w & 3;
    float acc3[2][4];
    #pragma unroll
    for (int h = 0; h < 2; ++h)
        #pragma unroll
        for (int e = 0; e < 4; ++e) acc3[h][e] = 0.0f;
    for (int s = 0; s < 8; ++s) {
        const int cb = s & 1;
        cpa_wait<0>();
        __syncthreads();                          // publishes boundary-2 stores at s==0
        if (s < 7) { fillB(Wqf + (s + 1) * 2048, 512, cb ^ 1); CPA_COMMIT(); }
        const float* bx = sB + cb * 8192;
        #pragma unroll
        for (int kk = 0; kk < 4; ++kk) {
            uint4 a = *reinterpret_cast<const uint4*>(sAct + (mi3 * 32 + s * 4 + kk) * 132 + lane * 4);
            uint4 b = *reinterpret_cast<const uint4*>(bx + (kk * 4 + nj3) * 128 + lane * 4);
            mma8(acc3[0], a, b.x, b.y);
            mma8(acc3[1], a, b.z, b.w);
        }
    }

    // ---- Epilogue: p = sum tanh(C3 + bq)*Wh ----
    float p = 0.0f;
    #pragma unroll
    for (int h = 0; h < 2; ++h) {
        const int col0 = nj3 * 16 + h * 8 + 2 * tg;
        const float* d = acc3[h];
        p += tanhf(d[0] + bqs[col0]) * whs[col0];
        p += tanhf(d[2] + bqs[col0]) * whs[col0];
        p += tanhf(d[1] + bqs[col0 + 1]) * whs[col0 + 1];
        p += tanhf(d[3] + bqs[col0 + 1]) * whs[col0 + 1];
    }
    #pragma unroll
    for (int off = 16; off > 0; off >>= 1)
        p += __shfl_down_sync(0xffffffffu, p, off);
    __syncthreads();
    if ((t & 31) == 0) red[w] = p;
    __syncthreads();
    if (t == 0) {
        float s = 0.0f;
        #pragma unroll
        for (int i = 0; i < 8; ++i) s += red[i];
        g_part[blockIdx.x] = s;
        __threadfence();
        unsigned int v = atomicAdd(&g_cnt, 1u);
        flg[0] = (v == NBLK - 1) ? 1.0f : 0.0f;
    }
    __syncthreads();

    // ---- Last CTA: final reduction (fixed order -> deterministic) ----
    if (flg[0] != 0.0f) {
        __threadfence();
        float v = g_part[t];
        #pragma unroll
        for (int off = 16; off > 0; off >>= 1)
            v += __shfl_down_sync(0xffffffffu, v, off);
        if ((t & 31) == 0) red[w] = v;
        __syncthreads();
        if (t == 0) {
            float s = 0.0f;
            #pragma unroll
            for (int i = 0; i < 8; ++i) s += red[i];
            out[0] = s + bh[0];
            g_cnt = 0;
        }
    }
}

extern "C" void kernel_launch(void* const* d_in, const int* in_sizes, int n_in,
                              void* d_out, int out_size)
{
    const float* X  = (const float*)d_in[0];
    const float* W1 = (const float*)d_in[1];
    const float* b1 = (const float*)d_in[2];
    const float* W2 = (const float*)d_in[3];
    const float* b2 = (const float*)d_in[4];
    const float* Wq = (const float*)d_in[5];
    const float* bq = (const float*)d_in[6];
    const float* Wh = (const float*)d_in[7];
    const float* bh = (const float*)d_in[8];

    conv_w<<<208, 256>>>(W1, W2, Wq);
    cudaFuncSetAttribute(fused_mma, cudaFuncAttributeMaxDynamicSharedMemorySize, SMEM_BYTES);
    fused_mma<<<NBLK, THREADS, SMEM_BYTES>>>(X, b1, b2, bq, Wh, bh, (float*)d_out);
}